// round 16
// baseline (speedup 1.0000x reference)
#include <cuda_runtime.h>
#include <math.h>
#include <stdint.h>

#define TNUM 4096
#define CH 128
#define NE 16
#define KB 32
#define VSZ 50257
#define NTILES 393   // ceil(50257/128)

// scratch (static device arrays — no allocation)
__device__ float g_x [TNUM*CH];
__device__ float g_xf[TNUM*CH];
__device__ float g_wtf[VSZ*CH];   // Wlm pre-rounded to tf32 (RNA), 25.7MB

__device__ __forceinline__ uint32_t f2tf(float f) {
    uint32_t r; asm("cvt.rna.tf32.f32 %0, %1;" : "=r"(r) : "f"(f)); return r;
}
__device__ __forceinline__ uint32_t s2u(const void* p) {
    uint32_t a;
    asm("{ .reg .u64 t; cvta.to.shared.u64 t, %1; cvt.u32.u64 %0, t; }" : "=r"(a) : "l"(p));
    return a;
}

// ==================== K0: Wlm -> tf32-rounded copy ====================
__global__ __launch_bounds__(512) void k0(const float* __restrict__ Wlm)
{
    int i = blockIdx.x * 512 + threadIdx.x;
    const int n4 = (VSZ * CH) / 4;
    if (i < n4) {
        float4 v = *(const float4*)&Wlm[(size_t)i * 4];
        uint4 o;
        o.x = f2tf(v.x); o.y = f2tf(v.y); o.z = f2tf(v.z); o.w = f2tf(v.w);
        *(uint4*)&g_wtf[(size_t)i * 4] = o;
    }
}

// ==================== K123: fused embed+LN1+route+q | attention | Wo+LN2+MLP ====
#define TBF 32
#define QSTR 132
#define F_SMEM 73856

__device__ __forceinline__ void k2_issue(const float* __restrict__ src, float* dst, int tid) {
    #pragma unroll
    for (int it = 0; it < 4; it++) {
        int i = tid + it * 256;
        int r = i >> 5, c4 = i & 31;
        uint32_t d = s2u(&dst[r * QSTR + c4 * 4]);
        asm volatile("cp.async.cg.shared.global [%0], [%1], 16;"
                     :: "r"(d), "l"(src + r * CH + c4 * 4) : "memory");
    }
    asm volatile("cp.async.commit_group;" ::: "memory");
}

__global__ __launch_bounds__(256) void k123(const int* __restrict__ ids,
        const float* __restrict__ emb, const float* __restrict__ router,
        const float* __restrict__ Wq, const float* __restrict__ g1,
        const float* __restrict__ b1, float* __restrict__ gate_out,
        const float* __restrict__ kexp, const float* __restrict__ vexp,
        const float* __restrict__ skv, const float* __restrict__ svv,
        const float* __restrict__ kvg,
        const float* __restrict__ Wo, const float* __restrict__ Wm,
        const float* __restrict__ bm, const float* __restrict__ g2,
        const float* __restrict__ b2)
{
    int bx = blockIdx.x;
    int tid = threadIdx.x;

    extern __shared__ float sp[];
    float* R0  = sp;
    float* R1  = sp + 4224;
    float* R2  = sp + 8448;
    float* R3  = sp + 12672;
    float* sS  = sp + 16896;
    float* sRW = sp + 17952;
    float* bufs[3] = { R0, R1, R3 };

    int t0 = bx * TBF;
    int wid = tid >> 5, lid = tid & 31;
    int td = tid & 31, tt = tid >> 5;

    #pragma unroll
    for (int i = 0; i < 4; i++) {
        int t = wid * 4 + i;
        int id = ids[t0 + t];
        float4 v = __ldg((const float4*)&emb[(size_t)id * CH + lid * 4]);
        *(float4*)&g_x[(size_t)(t0 + t) * CH + lid * 4] = v;
        float s = v.x + v.y + v.z + v.w;
        #pragma unroll
        for (int o = 16; o; o >>= 1) s += __shfl_xor_sync(0xffffffffu, s, o);
        float mu = s * (1.f/128.f);
        float4 d; d.x = v.x - mu; d.y = v.y - mu; d.z = v.z - mu; d.w = v.w - mu;
        float q2 = d.x*d.x + d.y*d.y + d.z*d.z + d.w*d.w;
        #pragma unroll
        for (int o = 16; o; o >>= 1) q2 += __shfl_xor_sync(0xffffffffu, q2, o);
        float inv = rsqrtf(q2 * (1.f/128.f) + 1e-5f);
        float4 g4 = __ldg((const float4*)&g1[lid * 4]);
        float4 b4 = __ldg((const float4*)&b1[lid * 4]);
        float4 o4;
        o4.x = d.x * inv * g4.x + b4.x;
        o4.y = d.y * inv * g4.y + b4.y;
        o4.z = d.z * inv * g4.z + b4.z;
        o4.w = d.w * inv * g4.w + b4.w;
        *(float4*)&R0[t * QSTR + lid * 4] = o4;
    }
    for (int i = tid; i < 16 * 32; i += 256) {
        int e = i >> 5, c4 = i & 31;
        *(float4*)&R1[e * QSTR + c4 * 4] = __ldg((const float4*)&router[(size_t)e * CH + c4 * 4]);
    }
    __syncthreads();

    {
        int t = tid >> 3, eg = tid & 7;
        float a0 = 0.f, a1 = 0.f;
        #pragma unroll 8
        for (int c4 = 0; c4 < 32; c4++) {
            float4 xv = *(float4*)&R0[t * QSTR + c4 * 4];
            float4 r0 = *(float4*)&R1[(2*eg)   * QSTR + c4 * 4];
            float4 r1 = *(float4*)&R1[(2*eg+1) * QSTR + c4 * 4];
            a0 += xv.x*r0.x + xv.y*r0.y + xv.z*r0.z + xv.w*r0.w;
            a1 += xv.x*r1.x + xv.y*r1.y + xv.z*r1.z + xv.w*r1.w;
        }
        sS[t * 33 + 2*eg] = a0; sS[t * 33 + 2*eg + 1] = a1;
    }
    __syncthreads();

    for (int i = tid; i < TBF * NE; i += 256)
        gate_out[(size_t)t0 * NE + i] = sS[(i >> 4) * 33 + (i & 15)];
    if (tid < TBF) {
        float mx = -1e30f;
        #pragma unroll
        for (int e = 0; e < NE; e++) mx = fmaxf(mx, sS[tid * 33 + e]);
        float ss = 0.f;
        #pragma unroll
        for (int e = 0; e < NE; e++) ss += __expf(sS[tid * 33 + e] - mx);
        float inv = 1.f / ss;
        #pragma unroll
        for (int e = 0; e < NE; e++)
            sRW[tid * NE + e] = __expf(sS[tid * 33 + e] - mx) * inv;
    }
    __syncthreads();

    #pragma unroll
    for (int dc = 0; dc < 4; dc++) {
        for (int i = tid; i < 32 * 32; i += 256) {
            int r = i >> 5, c4 = i & 31;
            *(float4*)&R1[r * QSTR + c4 * 4] =
                __ldg((const float4*)&Wq[(size_t)(dc * 32 + r) * CH + c4 * 4]);
        }
        __syncthreads();
        float acc[4] = {0.f, 0.f, 0.f, 0.f};
        #pragma unroll 4
        for (int c4 = 0; c4 < 32; c4++) {
            float4 wv = *(float4*)&R1[td * QSTR + c4 * 4];
            #pragma unroll
            for (int i = 0; i < 4; i++) {
                float4 xv = *(float4*)&R0[(tt * 4 + i) * QSTR + c4 * 4];
                acc[i] += xv.x*wv.x + xv.y*wv.y + xv.z*wv.z + xv.w*wv.w;
            }
        }
        __syncthreads();
        #pragma unroll
        for (int i = 0; i < 4; i++)
            R2[(tt * 4 + i) * QSTR + dc * 32 + td] = acc[i];
    }
    __syncthreads();

    float g = 1.f / (1.f + __expf(-kvg[0]));
    int t = tid >> 3, kg = tid & 7;
    float sdyn[4] = {0,0,0,0}, sstat[4] = {0,0,0,0};

    k2_issue(kexp, bufs[0], tid);
    for (int e = 0; e <= NE; e++) {
        if (e + 1 <= NE) {
            const float* s = (e + 1 < NE) ? kexp + (size_t)(e + 1) * KB * CH : skv;
            k2_issue(s, bufs[(e + 1) % 3], tid);
            asm volatile("cp.async.wait_group 1;" ::: "memory");
        } else {
            asm volatile("cp.async.wait_group 0;" ::: "memory");
        }
        __syncthreads();
        const float* bf = bufs[e % 3];
        float dj[4] = {0,0,0,0};
        const float4* qp = (const float4*)(R2 + t * QSTR);
        #pragma unroll 4
        for (int c4 = 0; c4 < 32; c4++) {
            float4 qv = qp[c4];
            #pragma unroll
            for (int j = 0; j < 4; j++) {
                float4 kv = *(const float4*)(bf + (kg + 8*j) * QSTR + 4 * c4);
                dj[j] += qv.x*kv.x + qv.y*kv.y + qv.z*kv.z + qv.w*kv.w;
            }
        }
        if (e < NE) {
            float rwv = sRW[t * NE + e];
            #pragma unroll
            for (int j = 0; j < 4; j++) sdyn[j] += rwv * dj[j];
        } else {
            #pragma unroll
            for (int j = 0; j < 4; j++) sstat[j] = dj[j];
        }
    }

    const float scale = 0.08838834764831845f;
    #pragma unroll
    for (int j = 0; j < 4; j++)
        sS[t * 33 + kg + 8*j] = (g * sdyn[j] + (1.f - g) * sstat[j]) * scale;
    __syncthreads();

    k2_issue(vexp, bufs[0], tid);

    if (tid < TBF) {
        float mx = -1e30f;
        #pragma unroll
        for (int k = 0; k < KB; k++) mx = fmaxf(mx, sS[tid * 33 + k]);
        float ssum = 0.f;
        #pragma unroll
        for (int k = 0; k < KB; k++) { float ev = __expf(sS[tid * 33 + k] - mx); sS[tid * 33 + k] = ev; ssum += ev; }
        float inv = 1.f / ssum;
        #pragma unroll
        for (int k = 0; k < KB; k++) sS[tid * 33 + k] *= inv;
    }
    __syncthreads();

    float acc[16];
    #pragma unroll
    for (int i = 0; i < 16; i++) acc[i] = 0.f;

    for (int e = 0; e <= NE; e++) {
        if (e + 1 <= NE) {
            const float* s = (e + 1 < NE) ? vexp + (size_t)(e + 1) * KB * CH : svv;
            k2_issue(s, bufs[(e + 1) % 3], tid);
            asm volatile("cp.async.wait_group 1;" ::: "memory");
        } else {
            asm volatile("cp.async.wait_group 0;" ::: "memory");
        }
        __syncthreads();
        const float* bf = bufs[e % 3];
        float we = (e < NE) ? g * sRW[t * NE + e] : (1.f - g);
        #pragma unroll 4
        for (int k = 0; k < KB; k++) {
            float w = we * sS[t * 33 + k];
            #pragma unroll
            for (int j = 0; j < 4; j++) {
                float4 vv = *(const float4*)(bf + k * QSTR + 4 * (kg + 8*j));
                acc[j*4+0] += w*vv.x; acc[j*4+1] += w*vv.y;
                acc[j*4+2] += w*vv.z; acc[j*4+3] += w*vv.w;
            }
        }
    }
    __syncthreads();

    #pragma unroll
    for (int j = 0; j < 4; j++) {
        float4 o;
        o.x = acc[j*4+0]; o.y = acc[j*4+1]; o.z = acc[j*4+2]; o.w = acc[j*4+3];
        *(float4*)&R0[t * QSTR + 4 * (kg + 8*j)] = o;
    }
    __syncthreads();

    float x2r[4][4];
    #pragma unroll
    for (int dc = 0; dc < 4; dc++) {
        for (int i = tid; i < 32 * 32; i += 256) {
            int r = i >> 5, c4 = i & 31;
            *(float4*)&R1[r * QSTR + c4 * 4] =
                __ldg((const float4*)&Wo[(size_t)(dc * 32 + r) * CH + c4 * 4]);
        }
        __syncthreads();
        float a2[4] = {0.f, 0.f, 0.f, 0.f};
        #pragma unroll 4
        for (int c4 = 0; c4 < 32; c4++) {
            float4 wv = *(float4*)&R1[td * QSTR + c4 * 4];
            #pragma unroll
            for (int i = 0; i < 4; i++) {
                float4 xv = *(float4*)&R0[(tt * 4 + i) * QSTR + c4 * 4];
                a2[i] += xv.x*wv.x + xv.y*wv.y + xv.z*wv.z + xv.w*wv.w;
            }
        }
        #pragma unroll
        for (int i = 0; i < 4; i++)
            x2r[dc][i] = a2[i] + g_x[(size_t)(t0 + tt * 4 + i) * CH + dc * 32 + td];
        __syncthreads();
    }

    #pragma unroll
    for (int dc = 0; dc < 4; dc++)
        #pragma unroll
        for (int i = 0; i < 4; i++)
            R0[(tt * 4 + i) * QSTR + dc * 32 + td] = x2r[dc][i];
    __syncthreads();

    #pragma unroll
    for (int i = 0; i < 4; i++) {
        int tk = tt * 4 + i;
        float4 v = *(float4*)&R0[tk * QSTR + td * 4];
        float s = v.x + v.y + v.z + v.w;
        #pragma unroll
        for (int o = 16; o; o >>= 1) s += __shfl_xor_sync(0xffffffffu, s, o);
        float mu = s * (1.f/128.f);
        float4 d; d.x = v.x - mu; d.y = v.y - mu; d.z = v.z - mu; d.w = v.w - mu;
        float q2 = d.x*d.x + d.y*d.y + d.z*d.z + d.w*d.w;
        #pragma unroll
        for (int o = 16; o; o >>= 1) q2 += __shfl_xor_sync(0xffffffffu, q2, o);
        float inv = rsqrtf(q2 * (1.f/128.f) + 1e-5f);
        float4 g4 = __ldg((const float4*)&g2[td * 4]);
        float4 b4 = __ldg((const float4*)&b2[td * 4]);
        float4 o4;
        o4.x = d.x * inv * g4.x + b4.x;
        o4.y = d.y * inv * g4.y + b4.y;
        o4.z = d.z * inv * g4.z + b4.z;
        o4.w = d.w * inv * g4.w + b4.w;
        *(float4*)&R0[tk * QSTR + td * 4] = o4;
    }
    __syncthreads();

    #pragma unroll
    for (int dc = 0; dc < 4; dc++) {
        for (int i = tid; i < 32 * 32; i += 256) {
            int r = i >> 5, c4 = i & 31;
            *(float4*)&R1[r * QSTR + c4 * 4] =
                __ldg((const float4*)&Wm[(size_t)(dc * 32 + r) * CH + c4 * 4]);
        }
        __syncthreads();
        float a2[4] = {0.f, 0.f, 0.f, 0.f};
        #pragma unroll 4
        for (int c4 = 0; c4 < 32; c4++) {
            float4 wv = *(float4*)&R1[td * QSTR + c4 * 4];
            #pragma unroll
            for (int i = 0; i < 4; i++) {
                float4 xv = *(float4*)&R0[(tt * 4 + i) * QSTR + c4 * 4];
                a2[i] += xv.x*wv.x + xv.y*wv.y + xv.z*wv.z + xv.w*wv.w;
            }
        }
        float bmv = __ldg(&bm[dc * 32 + td]);
        #pragma unroll
        for (int i = 0; i < 4; i++)
            g_xf[(size_t)(t0 + tt * 4 + i) * CH + dc * 32 + td] = x2r[dc][i] + bmv + a2[i];
        __syncthreads();
    }
}

// ==================== K4: LM head GEMM (m-pair persistent, cp.async B, TS MMA) ====
// Each B tile feeds TWO MMAs (m-pair): TMEM = D0,D1,A0,A1 (4 x 128 cols).
#if defined(__CUDA_ARCH__) && (__CUDA_ARCH__ == 1030) && defined(__CUDA_ARCH_FEAT_SM103_ALL)
#define HAS_TCGEN05 1
#else
#define HAS_TCGEN05 0
#endif

#define K4T 512
#define K4GRID 148
#define K4SUP (16 * NTILES)       // 6288 super-tiles (m-pair x n)
#define K4CHUNK 43                // ceil(6288/148)
#define SMB0 0
#define SMB1 65536
#define SCR  131072
#define K4_SMEM 196608

#define TM_D0 0
#define TM_D1 128
#define TM_A0 256
#define TM_A1 384

#if HAS_TCGEN05

__device__ __forceinline__ bool elect1() {
    uint32_t p;
    asm volatile("{ .reg .pred p; elect.sync _|p, 0xFFFFFFFF; selp.b32 %0, 1, 0, p; }" : "=r"(p));
    return p != 0;
}
__device__ __forceinline__ void mbar_init(uint32_t a, uint32_t cnt) {
    asm volatile("mbarrier.init.shared.b64 [%0], %1;" :: "r"(a), "r"(cnt) : "memory");
}
__device__ __forceinline__ void mbar_wait(uint32_t a, uint32_t ph) {
    asm volatile(
        "{\n\t.reg .pred P;\n"
        "W_%=:\n\t"
        "mbarrier.try_wait.parity.acquire.cta.shared::cta.b64 P, [%0], %1, 0x989680;\n\t"
        "@P bra D_%=;\n\t"
        "bra W_%=;\n"
        "D_%=:\n\t}"
        :: "r"(a), "r"(ph) : "memory");
}
__device__ __forceinline__ void sts128(uint32_t a, uint32_t r0, uint32_t r1, uint32_t r2, uint32_t r3) {
    asm volatile("st.shared.v4.b32 [%0], {%1, %2, %3, %4};" :: "r"(a), "r"(r0), "r"(r1), "r"(r2), "r"(r3) : "memory");
}
__device__ __forceinline__ void mma_tf32_ts(uint32_t d, uint32_t a, uint64_t bd, uint32_t idesc, bool accum) {
    uint32_t en = accum ? 1u : 0u;
    asm volatile(
        "{\n\t.reg .pred p;\n\t"
        "setp.ne.u32 p, %5, 0;\n\t"
        "tcgen05.mma.cta_group::1.kind::tf32 [%0], [%1], %2, %3, {%4, %4, %4, %4}, p;\n\t}"
        :: "r"(d), "r"(a), "l"(bd), "r"(idesc), "r"(0u), "r"(en) : "memory");
}
__device__ __forceinline__ void mma_commit(uint32_t mbar) {
    asm volatile("tcgen05.commit.cta_group::1.mbarrier::arrive::one.shared::cluster.b64 [%0];" :: "r"(mbar) : "memory");
}
__device__ __forceinline__ uint64_t mk_desc(uint32_t addr) {
    const uint64_t base = (uint64_t(2) << 61) | (uint64_t(1) << 46) | (uint64_t(64) << 32) | (uint64_t(1) << 16);
    return base | ((uint64_t)(addr >> 4) & 0x3FFF);
}

#define LDTM32(r, a) \
    asm volatile( \
        "tcgen05.ld.sync.aligned.32x32b.x32.b32 " \
        "{%0, %1, %2, %3, %4, %5, %6, %7, " \
        " %8, %9, %10, %11, %12, %13, %14, %15, " \
        " %16, %17, %18, %19, %20, %21, %22, %23, " \
        " %24, %25, %26, %27, %28, %29, %30, %31}, [%32];" \
        : "=r"((r)[0]),  "=r"((r)[1]),  "=r"((r)[2]),  "=r"((r)[3]), \
          "=r"((r)[4]),  "=r"((r)[5]),  "=r"((r)[6]),  "=r"((r)[7]), \
          "=r"((r)[8]),  "=r"((r)[9]),  "=r"((r)[10]), "=r"((r)[11]), \
          "=r"((r)[12]), "=r"((r)[13]), "=r"((r)[14]), "=r"((r)[15]), \
          "=r"((r)[16]), "=r"((r)[17]), "=r"((r)[18]), "=r"((r)[19]), \
          "=r"((r)[20]), "=r"((r)[21]), "=r"((r)[22]), "=r"((r)[23]), \
          "=r"((r)[24]), "=r"((r)[25]), "=r"((r)[26]), "=r"((r)[27]), \
          "=r"((r)[28]), "=r"((r)[29]), "=r"((r)[30]), "=r"((r)[31]) \
        : "r"(a))

#define STTM32(a, r) \
    asm volatile( \
        "tcgen05.st.sync.aligned.32x32b.x32.b32 [%0], " \
        "{%1, %2, %3, %4, %5, %6, %7, %8, " \
        " %9, %10, %11, %12, %13, %14, %15, %16, " \
        " %17, %18, %19, %20, %21, %22, %23, %24, " \
        " %25, %26, %27, %28, %29, %30, %31, %32};" \
        :: "r"(a), \
           "r"((r)[0]),  "r"((r)[1]),  "r"((r)[2]),  "r"((r)[3]), \
           "r"((r)[4]),  "r"((r)[5]),  "r"((r)[6]),  "r"((r)[7]), \
           "r"((r)[8]),  "r"((r)[9]),  "r"((r)[10]), "r"((r)[11]), \
           "r"((r)[12]), "r"((r)[13]), "r"((r)[14]), "r"((r)[15]), \
           "r"((r)[16]), "r"((r)[17]), "r"((r)[18]), "r"((r)[19]), \
           "r"((r)[20]), "r"((r)[21]), "r"((r)[22]), "r"((r)[23]), \
           "r"((r)[24]), "r"((r)[25]), "r"((r)[26]), "r"((r)[27]), \
           "r"((r)[28]), "r"((r)[29]), "r"((r)[30]), "r"((r)[31]) \
        : "memory")

#define K4_IDESC ((1u<<4) | (2u<<7) | (2u<<10) | (16u<<17) | (8u<<24))

__device__ __forceinline__ void k4_load_tile_ca(uint32_t sdst, int row0, int tid)
{
    #pragma unroll
    for (int it = 0; it < 8; it++) {
        int f = tid + it * K4T;
        int r = f >> 5, q = f & 31;
        int kc = q >> 3, c4 = q & 7;
        uint32_t off = (uint32_t)(kc * 16384 + r * 128 + c4 * 16);
        off = off ^ ((off >> 3) & 0x70);
        int row = row0 + r;
        int ok = (row < VSZ);
        const float* gsrc = &g_wtf[(size_t)(ok ? row : 0) * CH + q * 4];
        int sz = ok ? 16 : 0;
        asm volatile("cp.async.cg.shared.global [%0], [%1], 16, %2;"
                     :: "r"(sdst + off), "l"(gsrc), "r"(sz) : "memory");
    }
}

// Epilogue v6 (round-15): conflict-free LDS.128 + shfl alignment shift.
__device__ __forceinline__ void k4_epilogue(uint32_t dt, float* __restrict__ scr,
                                            int m0, int n0,
                                            float* __restrict__ out, int tid)
{
    int w = tid >> 5, lid = tid & 31;
    int row = (w & 3) * 32 + lid;
    int cb  = (w >> 2) * 32;
    uint32_t scr_u = s2u(scr);

    {
        uint32_t r[32];
        LDTM32(r, dt + cb);
        asm volatile("tcgen05.wait::ld.sync.aligned;" ::: "memory");
        #pragma unroll
        for (int gq = 0; gq < 8; gq++) {
            int cg = (cb >> 2) + gq;
            int sg = cg ^ (row & 31);
            sts128(scr_u + (uint32_t)(row * 128 + sg * 4) * 4,
                   r[4*gq], r[4*gq+1], r[4*gq+2], r[4*gq+3]);
        }
    }
    __syncthreads();

    if (n0 + 128 <= VSZ) {
        #pragma unroll
        for (int itr = 0; itr < 8; itr++) {
            int r2 = w * 8 + itr;
            int m  = m0 + r2;
            int c0 = (4 - (m & 3)) & 3;
            int sw = r2 & 31;
            float* orow = out + (size_t)m * VSZ + n0;

            int sg = lid ^ sw;
            float4 v = *(const float4*)&scr[r2 * 128 + sg * 4];

            if (c0 == 0) {
                *(float4*)(orow + 4 * lid) = v;
            } else {
                float vn0 = __shfl_down_sync(0xffffffffu, v.x, 1);
                float vn1 = __shfl_down_sync(0xffffffffu, v.y, 1);
                float vn2 = __shfl_down_sync(0xffffffffu, v.z, 1);
                float a0 = v.x, a1 = v.y, a2v = v.z, a3 = v.w;
                float4 o;
                if (c0 == 1)      { o.x = a1;  o.y = a2v; o.z = a3;  o.w = vn0; }
                else if (c0 == 2) { o.x = a2v; o.y = a3;  o.z = vn0; o.w = vn1; }
                else              { o.x = a3;  o.y = vn0; o.z = vn1; o.w = vn2; }
                if (lid < 31)
                    *(float4*)(orow + c0 + 4 * lid) = o;
                if (lid < c0)
                    orow[lid] = scr[r2 * 128 + (0 ^ sw) * 4 + lid];
                if (lid == 31) {
                    float tv[4] = { a0, a1, a2v, a3 };
                    #pragma unroll
                    for (int k = 0; k < 3; k++)
                        if (k < 4 - c0) orow[c0 + 124 + k] = tv[k + c0];
                }
            }
        }
    } else {
        for (int itr = 0; itr < 8; itr++) {
            int r2 = w * 8 + itr;
            int sw = r2 & 31;
            float* orow = out + (size_t)(m0 + r2) * VSZ;
            #pragma unroll
            for (int k = 0; k < 4; k++) {
                int col = lid + 32 * k;
                if (n0 + col < VSZ) {
                    int sg2 = (col >> 2) ^ sw;
                    orow[n0 + col] = scr[r2 * 128 + sg2 * 4 + (col & 3)];
                }
            }
        }
    }
}
#endif  // HAS_TCGEN05

__global__ void __launch_bounds__(K4T, 1) k4mma(const float* __restrict__ Wlm,
                                                float* __restrict__ out)
{
    extern __shared__ __align__(1024) char smem[];
    int tid = threadIdx.x;
    int c = blockIdx.x;
    int T0 = c * K4CHUNK;
    int T1 = T0 + K4CHUNK; if (T1 > K4SUP) T1 = K4SUP;

#if HAS_TCGEN05
    __shared__ __align__(16) unsigned long long s_mbar[1];
    __shared__ uint32_t s_tmem;

    int wid = tid >> 5;
    uint32_t sb = s2u(smem);
    float* scr = (float*)(smem + SCR);
    uint32_t mb = s2u(&s_mbar[0]);

    if (wid == 0) {
        asm volatile("tcgen05.alloc.cta_group::1.sync.aligned.shared::cta.b32 [%0], %1;"
                     :: "r"(s2u(&s_tmem)), "r"(512u) : "memory");
        asm volatile("tcgen05.relinquish_alloc_permit.cta_group::1.sync.aligned;");
    }
    if (tid == 0) mbar_init(mb, 1);
    __syncthreads();
    uint32_t tmem;
    asm volatile("ld.shared.b32 %0, [%1];" : "=r"(tmem) : "r"(s2u(&s_tmem)));

    uint64_t bdesc[2] = { mk_desc(sb + SMB0), mk_desc(sb + SMB1) };
    int ph = 0;
    int s = 0;   // slot counter (B buffer parity)

    while (T0 < T1) {
        int mp = T0 / NTILES;
        int n0idx = T0 - mp * NTILES;
        int segend = (mp + 1) * NTILES; if (segend > T1) segend = T1;
        int nt = segend - T0;
        int m0 = mp * 256;   // pair base: rows m0..m0+255

        // A0, A1 -> TMEM (prev segment's MMAs drained by its final mbar_wait)
        if (tid < 256) {
            int half = tid >> 7;            // 0 -> A0, 1 -> A1
            int lt = tid & 127;
            uint32_t warp_off = (uint32_t)(lt >> 5) << 21;
            uint32_t abase = half ? TM_A1 : TM_A0;
            const float* arow = &g_xf[(size_t)(m0 + half * 128 + lt) * CH];
            #pragma unroll
            for (int q = 0; q < 4; q++) {
                uint32_t ar[32];
                #pragma unroll
                for (int j = 0; j < 32; j++) ar[j] = f2tf(arow[q * 32 + j]);
                STTM32(tmem + abase + q * 32 + warp_off, ar);
            }
            asm volatile("tcgen05.wait::st.sync.aligned;" ::: "memory");
            asm volatile("tcgen05.fence::before_thread_sync;" ::: "memory");
        }
        // first B of segment
        k4_load_tile_ca(sb + ((s & 1) ? SMB1 : SMB0), n0idx * 128, tid);
        asm volatile("cp.async.commit_group;" ::: "memory");

        for (int i = 0; i < nt; i++) {
            int b = s & 1;
            int n0 = (n0idx + i) * 128;

            // B(n) visible; A ready; previous epilogues' scratch reads done
            asm volatile("cp.async.wait_group 0;" ::: "memory");
            asm volatile("fence.proxy.async.shared::cta;" ::: "memory");
            __syncthreads();

            // two MMAs off one B tile, one commit
            if (wid == 0 && elect1()) {
                asm volatile("tcgen05.fence::after_thread_sync;" ::: "memory");
                #pragma unroll
                for (int st = 0; st < 16; st++) {
                    uint64_t koff = (uint64_t)((st >> 2) * 1024 + (st & 3) * 2);
                    mma_tf32_ts(tmem + TM_D0, tmem + TM_A0 + st * 8,
                                bdesc[b] + koff, K4_IDESC, st > 0);
                }
                #pragma unroll
                for (int st = 0; st < 16; st++) {
                    uint64_t koff = (uint64_t)((st >> 2) * 1024 + (st & 3) * 2);
                    mma_tf32_ts(tmem + TM_D1, tmem + TM_A1 + st * 8,
                                bdesc[b] + koff, K4_IDESC, st > 0);
                }
                mma_commit(mb);
            }

            // prefetch B(n+1) into the other buffer (overlaps the MMA wait)
            if (i + 1 < nt) {
                k4_load_tile_ca(sb + ((b ^ 1) ? SMB1 : SMB0), (n0idx + i + 1) * 128, tid);
                asm volatile("cp.async.commit_group;" ::: "memory");
            }

            // wait both MMAs, then drain D0/D1 (B(n+1) streams meanwhile)
            mbar_wait(mb, ph); ph ^= 1;
            asm volatile("tcgen05.fence::after_thread_sync;" ::: "memory");
            k4_epilogue(tmem + TM_D0, scr, m0,       n0, out, tid);
            __syncthreads();
            k4_epilogue(tmem + TM_D1, scr, m0 + 128, n0, out, tid);

            s++;
        }
        T0 = segend;
    }

    __syncthreads();
    if (wid == 0) {
        asm volatile("tcgen05.dealloc.cta_group::1.sync.aligned.b32 %0, %1;"
                     :: "r"(tmem), "r"(512u));
    }
#else
    // -------- fallback: plain fp32 smem GEMM (baseline sm_103 target) --------
    float* sA = (float*)(smem + SCR);
    float* sB = (float*)(smem + SMB0);

    int tx = tid & 31, ty = tid >> 5;

    while (T0 < T1) {
        int mp = T0 / NTILES;
        int n = T0 - mp * NTILES;
        int n0 = n * 128;

        for (int h = 0; h < 2; h++) {
            int m0 = mp * 256 + h * 128;
            __syncthreads();
            for (int i = tid; i < 128 * 32; i += K4T) {
                int r = i >> 5, q = i & 31;
                *(float4*)&sA[r * 128 + q * 4] = *(const float4*)&g_xf[(size_t)(m0 + r) * CH + q * 4];
            }
            for (int i = tid; i < 128 * 32; i += K4T) {
                int r = i >> 5, q = i & 31;
                float4 v = make_float4(0.f, 0.f, 0.f, 0.f);
                if (n0 + r < VSZ)
                    v = *(const float4*)&Wlm[(size_t)(n0 + r) * CH + q * 4];
                *(float4*)&sB[r * 128 + q * 4] = v;
            }
            __syncthreads();

            float acc[8][4];
            #pragma unroll
            for (int i = 0; i < 8; i++)
                #pragma unroll
                for (int j = 0; j < 4; j++) acc[i][j] = 0.f;

            for (int k = 0; k < 128; k++) {
                float a[8], b[4];
                #pragma unroll
                for (int i = 0; i < 8; i++) a[i] = sA[(ty * 8 + i) * 128 + k];
                #pragma unroll
                for (int j = 0; j < 4; j++) b[j] = sB[(tx * 4 + j) * 128 + k];
                #pragma unroll
                for (int i = 0; i < 8; i++)
                    #pragma unroll
                    for (int j = 0; j < 4; j++) acc[i][j] += a[i] * b[j];
            }

            #pragma unroll
            for (int i = 0; i < 8; i++) {
                float* row = out + (size_t)(m0 + ty * 8 + i) * VSZ;
                #pragma unroll
                for (int j = 0; j < 4; j++) {
                    int nn = n0 + tx * 4 + j;
                    if (nn < VSZ) row[nn] = acc[i][j];
                }
            }
        }
        T0++;
    }
#endif
}

// ==================== launch ====================
extern "C" void kernel_launch(void* const* d_in, const int* in_sizes, int n_in,
                              void* d_out, int out_size)
{
    const int*   ids    = (const int*)  d_in[0];
    const float* emb    = (const float*)d_in[1];
    const float* router = (const float*)d_in[2];
    const float* kexp   = (const float*)d_in[3];
    const float* vexp   = (const float*)d_in[4];
    const float* skv    = (const float*)d_in[5];
    const float* svv    = (const float*)d_in[6];
    const float* kvg    = (const float*)d_in[7];
    const float* Wq     = (const float*)d_in[8];
    const float* Wo     = (const float*)d_in[9];
    const float* Wm     = (const float*)d_in[10];
    const float* bm     = (const float*)d_in[11];
    const float* g1     = (const float*)d_in[12];
    const float* b1     = (const float*)d_in[13];
    const float* g2     = (const float*)d_in[14];
    const float* b2     = (const float*)d_in[15];
    const float* Wlm    = (const float*)d_in[16];

    float* out = (float*)d_out;
    float* gate_out = out + ((size_t)out_size - (size_t)TNUM * NE);

    cudaFuncSetAttribute(k4mma, cudaFuncAttributeMaxDynamicSharedMemorySize, K4_SMEM);
    cudaFuncSetAttribute(k123, cudaFuncAttributeMaxDynamicSharedMemorySize, F_SMEM);

    k0<<<((VSZ*CH/4) + 511) / 512, 512>>>(Wlm);
    k123<<<128, 256, F_SMEM>>>(ids, emb, router, Wq, g1, b1, gate_out,
                               kexp, vexp, skv, svv, kvg,
                               Wo, Wm, bm, g2, b2);
    k4mma<<<K4GRID, K4T, K4_SMEM>>>(Wlm, out);
}

// round 17
// speedup vs baseline: 1.0287x; 1.0287x over previous
#include <cuda_runtime.h>
#include <math.h>
#include <stdint.h>

#define TNUM 4096
#define CH 128
#define NE 16
#define KB 32
#define VSZ 50257
#define NTILES 393   // ceil(50257/128)

// scratch (static device arrays — no allocation)
__device__ float g_x [TNUM*CH];
__device__ float g_xf[TNUM*CH];
__device__ float g_wtf[VSZ*CH];   // Wlm pre-rounded to tf32 (RNA), 25.7MB

__device__ __forceinline__ uint32_t f2tf(float f) {
    uint32_t r; asm("cvt.rna.tf32.f32 %0, %1;" : "=r"(r) : "f"(f)); return r;
}
__device__ __forceinline__ uint32_t s2u(const void* p) {
    uint32_t a;
    asm("{ .reg .u64 t; cvta.to.shared.u64 t, %1; cvt.u32.u64 %0, t; }" : "=r"(a) : "l"(p));
    return a;
}

// ==================== K0: Wlm -> tf32-rounded copy ====================
__global__ __launch_bounds__(512) void k0(const float* __restrict__ Wlm)
{
    int i = blockIdx.x * 512 + threadIdx.x;
    const int n4 = (VSZ * CH) / 4;
    if (i < n4) {
        float4 v = *(const float4*)&Wlm[(size_t)i * 4];
        uint4 o;
        o.x = f2tf(v.x); o.y = f2tf(v.y); o.z = f2tf(v.z); o.w = f2tf(v.w);
        *(uint4*)&g_wtf[(size_t)i * 4] = o;
    }
}

// ==================== K123: fused embed+LN1+route+q | attention | Wo+LN2+MLP ====
#define TBF 32
#define QSTR 132
#define F_SMEM 73856

__device__ __forceinline__ void k2_issue(const float* __restrict__ src, float* dst, int tid) {
    #pragma unroll
    for (int it = 0; it < 4; it++) {
        int i = tid + it * 256;
        int r = i >> 5, c4 = i & 31;
        uint32_t d = s2u(&dst[r * QSTR + c4 * 4]);
        asm volatile("cp.async.cg.shared.global [%0], [%1], 16;"
                     :: "r"(d), "l"(src + r * CH + c4 * 4) : "memory");
    }
    asm volatile("cp.async.commit_group;" ::: "memory");
}

__global__ __launch_bounds__(256) void k123(const int* __restrict__ ids,
        const float* __restrict__ emb, const float* __restrict__ router,
        const float* __restrict__ Wq, const float* __restrict__ g1,
        const float* __restrict__ b1, float* __restrict__ gate_out,
        const float* __restrict__ kexp, const float* __restrict__ vexp,
        const float* __restrict__ skv, const float* __restrict__ svv,
        const float* __restrict__ kvg,
        const float* __restrict__ Wo, const float* __restrict__ Wm,
        const float* __restrict__ bm, const float* __restrict__ g2,
        const float* __restrict__ b2)
{
    int bx = blockIdx.x;
    int tid = threadIdx.x;

    extern __shared__ float sp[];
    float* R0  = sp;
    float* R1  = sp + 4224;
    float* R2  = sp + 8448;
    float* R3  = sp + 12672;
    float* sS  = sp + 16896;
    float* sRW = sp + 17952;
    float* bufs[3] = { R0, R1, R3 };

    int t0 = bx * TBF;
    int wid = tid >> 5, lid = tid & 31;
    int td = tid & 31, tt = tid >> 5;

    #pragma unroll
    for (int i = 0; i < 4; i++) {
        int t = wid * 4 + i;
        int id = ids[t0 + t];
        float4 v = __ldg((const float4*)&emb[(size_t)id * CH + lid * 4]);
        *(float4*)&g_x[(size_t)(t0 + t) * CH + lid * 4] = v;
        float s = v.x + v.y + v.z + v.w;
        #pragma unroll
        for (int o = 16; o; o >>= 1) s += __shfl_xor_sync(0xffffffffu, s, o);
        float mu = s * (1.f/128.f);
        float4 d; d.x = v.x - mu; d.y = v.y - mu; d.z = v.z - mu; d.w = v.w - mu;
        float q2 = d.x*d.x + d.y*d.y + d.z*d.z + d.w*d.w;
        #pragma unroll
        for (int o = 16; o; o >>= 1) q2 += __shfl_xor_sync(0xffffffffu, q2, o);
        float inv = rsqrtf(q2 * (1.f/128.f) + 1e-5f);
        float4 g4 = __ldg((const float4*)&g1[lid * 4]);
        float4 b4 = __ldg((const float4*)&b1[lid * 4]);
        float4 o4;
        o4.x = d.x * inv * g4.x + b4.x;
        o4.y = d.y * inv * g4.y + b4.y;
        o4.z = d.z * inv * g4.z + b4.z;
        o4.w = d.w * inv * g4.w + b4.w;
        *(float4*)&R0[t * QSTR + lid * 4] = o4;
    }
    for (int i = tid; i < 16 * 32; i += 256) {
        int e = i >> 5, c4 = i & 31;
        *(float4*)&R1[e * QSTR + c4 * 4] = __ldg((const float4*)&router[(size_t)e * CH + c4 * 4]);
    }
    __syncthreads();

    {
        int t = tid >> 3, eg = tid & 7;
        float a0 = 0.f, a1 = 0.f;
        #pragma unroll 8
        for (int c4 = 0; c4 < 32; c4++) {
            float4 xv = *(float4*)&R0[t * QSTR + c4 * 4];
            float4 r0 = *(float4*)&R1[(2*eg)   * QSTR + c4 * 4];
            float4 r1 = *(float4*)&R1[(2*eg+1) * QSTR + c4 * 4];
            a0 += xv.x*r0.x + xv.y*r0.y + xv.z*r0.z + xv.w*r0.w;
            a1 += xv.x*r1.x + xv.y*r1.y + xv.z*r1.z + xv.w*r1.w;
        }
        sS[t * 33 + 2*eg] = a0; sS[t * 33 + 2*eg + 1] = a1;
    }
    __syncthreads();

    for (int i = tid; i < TBF * NE; i += 256)
        gate_out[(size_t)t0 * NE + i] = sS[(i >> 4) * 33 + (i & 15)];
    if (tid < TBF) {
        float mx = -1e30f;
        #pragma unroll
        for (int e = 0; e < NE; e++) mx = fmaxf(mx, sS[tid * 33 + e]);
        float ss = 0.f;
        #pragma unroll
        for (int e = 0; e < NE; e++) ss += __expf(sS[tid * 33 + e] - mx);
        float inv = 1.f / ss;
        #pragma unroll
        for (int e = 0; e < NE; e++)
            sRW[tid * NE + e] = __expf(sS[tid * 33 + e] - mx) * inv;
    }
    __syncthreads();

    #pragma unroll
    for (int dc = 0; dc < 4; dc++) {
        for (int i = tid; i < 32 * 32; i += 256) {
            int r = i >> 5, c4 = i & 31;
            *(float4*)&R1[r * QSTR + c4 * 4] =
                __ldg((const float4*)&Wq[(size_t)(dc * 32 + r) * CH + c4 * 4]);
        }
        __syncthreads();
        float acc[4] = {0.f, 0.f, 0.f, 0.f};
        #pragma unroll 4
        for (int c4 = 0; c4 < 32; c4++) {
            float4 wv = *(float4*)&R1[td * QSTR + c4 * 4];
            #pragma unroll
            for (int i = 0; i < 4; i++) {
                float4 xv = *(float4*)&R0[(tt * 4 + i) * QSTR + c4 * 4];
                acc[i] += xv.x*wv.x + xv.y*wv.y + xv.z*wv.z + xv.w*wv.w;
            }
        }
        __syncthreads();
        #pragma unroll
        for (int i = 0; i < 4; i++)
            R2[(tt * 4 + i) * QSTR + dc * 32 + td] = acc[i];
    }
    __syncthreads();

    float g = 1.f / (1.f + __expf(-kvg[0]));
    int t = tid >> 3, kg = tid & 7;
    float sdyn[4] = {0,0,0,0}, sstat[4] = {0,0,0,0};

    k2_issue(kexp, bufs[0], tid);
    for (int e = 0; e <= NE; e++) {
        if (e + 1 <= NE) {
            const float* s = (e + 1 < NE) ? kexp + (size_t)(e + 1) * KB * CH : skv;
            k2_issue(s, bufs[(e + 1) % 3], tid);
            asm volatile("cp.async.wait_group 1;" ::: "memory");
        } else {
            asm volatile("cp.async.wait_group 0;" ::: "memory");
        }
        __syncthreads();
        const float* bf = bufs[e % 3];
        float dj[4] = {0,0,0,0};
        const float4* qp = (const float4*)(R2 + t * QSTR);
        #pragma unroll 4
        for (int c4 = 0; c4 < 32; c4++) {
            float4 qv = qp[c4];
            #pragma unroll
            for (int j = 0; j < 4; j++) {
                float4 kv = *(const float4*)(bf + (kg + 8*j) * QSTR + 4 * c4);
                dj[j] += qv.x*kv.x + qv.y*kv.y + qv.z*kv.z + qv.w*kv.w;
            }
        }
        if (e < NE) {
            float rwv = sRW[t * NE + e];
            #pragma unroll
            for (int j = 0; j < 4; j++) sdyn[j] += rwv * dj[j];
        } else {
            #pragma unroll
            for (int j = 0; j < 4; j++) sstat[j] = dj[j];
        }
    }

    const float scale = 0.08838834764831845f;
    #pragma unroll
    for (int j = 0; j < 4; j++)
        sS[t * 33 + kg + 8*j] = (g * sdyn[j] + (1.f - g) * sstat[j]) * scale;
    __syncthreads();

    k2_issue(vexp, bufs[0], tid);

    if (tid < TBF) {
        float mx = -1e30f;
        #pragma unroll
        for (int k = 0; k < KB; k++) mx = fmaxf(mx, sS[tid * 33 + k]);
        float ssum = 0.f;
        #pragma unroll
        for (int k = 0; k < KB; k++) { float ev = __expf(sS[tid * 33 + k] - mx); sS[tid * 33 + k] = ev; ssum += ev; }
        float inv = 1.f / ssum;
        #pragma unroll
        for (int k = 0; k < KB; k++) sS[tid * 33 + k] *= inv;
    }
    __syncthreads();

    float acc[16];
    #pragma unroll
    for (int i = 0; i < 16; i++) acc[i] = 0.f;

    for (int e = 0; e <= NE; e++) {
        if (e + 1 <= NE) {
            const float* s = (e + 1 < NE) ? vexp + (size_t)(e + 1) * KB * CH : svv;
            k2_issue(s, bufs[(e + 1) % 3], tid);
            asm volatile("cp.async.wait_group 1;" ::: "memory");
        } else {
            asm volatile("cp.async.wait_group 0;" ::: "memory");
        }
        __syncthreads();
        const float* bf = bufs[e % 3];
        float we = (e < NE) ? g * sRW[t * NE + e] : (1.f - g);
        #pragma unroll 4
        for (int k = 0; k < KB; k++) {
            float w = we * sS[t * 33 + k];
            #pragma unroll
            for (int j = 0; j < 4; j++) {
                float4 vv = *(const float4*)(bf + k * QSTR + 4 * (kg + 8*j));
                acc[j*4+0] += w*vv.x; acc[j*4+1] += w*vv.y;
                acc[j*4+2] += w*vv.z; acc[j*4+3] += w*vv.w;
            }
        }
    }
    __syncthreads();

    #pragma unroll
    for (int j = 0; j < 4; j++) {
        float4 o;
        o.x = acc[j*4+0]; o.y = acc[j*4+1]; o.z = acc[j*4+2]; o.w = acc[j*4+3];
        *(float4*)&R0[t * QSTR + 4 * (kg + 8*j)] = o;
    }
    __syncthreads();

    float x2r[4][4];
    #pragma unroll
    for (int dc = 0; dc < 4; dc++) {
        for (int i = tid; i < 32 * 32; i += 256) {
            int r = i >> 5, c4 = i & 31;
            *(float4*)&R1[r * QSTR + c4 * 4] =
                __ldg((const float4*)&Wo[(size_t)(dc * 32 + r) * CH + c4 * 4]);
        }
        __syncthreads();
        float a2[4] = {0.f, 0.f, 0.f, 0.f};
        #pragma unroll 4
        for (int c4 = 0; c4 < 32; c4++) {
            float4 wv = *(float4*)&R1[td * QSTR + c4 * 4];
            #pragma unroll
            for (int i = 0; i < 4; i++) {
                float4 xv = *(float4*)&R0[(tt * 4 + i) * QSTR + c4 * 4];
                a2[i] += xv.x*wv.x + xv.y*wv.y + xv.z*wv.z + xv.w*wv.w;
            }
        }
        #pragma unroll
        for (int i = 0; i < 4; i++)
            x2r[dc][i] = a2[i] + g_x[(size_t)(t0 + tt * 4 + i) * CH + dc * 32 + td];
        __syncthreads();
    }

    #pragma unroll
    for (int dc = 0; dc < 4; dc++)
        #pragma unroll
        for (int i = 0; i < 4; i++)
            R0[(tt * 4 + i) * QSTR + dc * 32 + td] = x2r[dc][i];
    __syncthreads();

    #pragma unroll
    for (int i = 0; i < 4; i++) {
        int tk = tt * 4 + i;
        float4 v = *(float4*)&R0[tk * QSTR + td * 4];
        float s = v.x + v.y + v.z + v.w;
        #pragma unroll
        for (int o = 16; o; o >>= 1) s += __shfl_xor_sync(0xffffffffu, s, o);
        float mu = s * (1.f/128.f);
        float4 d; d.x = v.x - mu; d.y = v.y - mu; d.z = v.z - mu; d.w = v.w - mu;
        float q2 = d.x*d.x + d.y*d.y + d.z*d.z + d.w*d.w;
        #pragma unroll
        for (int o = 16; o; o >>= 1) q2 += __shfl_xor_sync(0xffffffffu, q2, o);
        float inv = rsqrtf(q2 * (1.f/128.f) + 1e-5f);
        float4 g4 = __ldg((const float4*)&g2[td * 4]);
        float4 b4 = __ldg((const float4*)&b2[td * 4]);
        float4 o4;
        o4.x = d.x * inv * g4.x + b4.x;
        o4.y = d.y * inv * g4.y + b4.y;
        o4.z = d.z * inv * g4.z + b4.z;
        o4.w = d.w * inv * g4.w + b4.w;
        *(float4*)&R0[tk * QSTR + td * 4] = o4;
    }
    __syncthreads();

    #pragma unroll
    for (int dc = 0; dc < 4; dc++) {
        for (int i = tid; i < 32 * 32; i += 256) {
            int r = i >> 5, c4 = i & 31;
            *(float4*)&R1[r * QSTR + c4 * 4] =
                __ldg((const float4*)&Wm[(size_t)(dc * 32 + r) * CH + c4 * 4]);
        }
        __syncthreads();
        float a2[4] = {0.f, 0.f, 0.f, 0.f};
        #pragma unroll 4
        for (int c4 = 0; c4 < 32; c4++) {
            float4 wv = *(float4*)&R1[td * QSTR + c4 * 4];
            #pragma unroll
            for (int i = 0; i < 4; i++) {
                float4 xv = *(float4*)&R0[(tt * 4 + i) * QSTR + c4 * 4];
                a2[i] += xv.x*wv.x + xv.y*wv.y + xv.z*wv.z + xv.w*wv.w;
            }
        }
        float bmv = __ldg(&bm[dc * 32 + td]);
        #pragma unroll
        for (int i = 0; i < 4; i++)
            g_xf[(size_t)(t0 + tt * 4 + i) * CH + dc * 32 + td] = x2r[dc][i] + bmv + a2[i];
        __syncthreads();
    }
}

// ==================== K4: LM head GEMM (m-pair, split-commit overlap) ====
#if defined(__CUDA_ARCH__) && (__CUDA_ARCH__ == 1030) && defined(__CUDA_ARCH_FEAT_SM103_ALL)
#define HAS_TCGEN05 1
#else
#define HAS_TCGEN05 0
#endif

#define K4T 512
#define K4GRID 148
#define K4SUP (16 * NTILES)       // 6288 super-tiles (m-pair x n)
#define K4CHUNK 43                // ceil(6288/148)
#define SMB0 0
#define SMB1 65536
#define SCR  131072
#define K4_SMEM 196608

#define TM_D0 0
#define TM_D1 128
#define TM_A0 256
#define TM_A1 384

#if HAS_TCGEN05

__device__ __forceinline__ bool elect1() {
    uint32_t p;
    asm volatile("{ .reg .pred p; elect.sync _|p, 0xFFFFFFFF; selp.b32 %0, 1, 0, p; }" : "=r"(p));
    return p != 0;
}
__device__ __forceinline__ void mbar_init(uint32_t a, uint32_t cnt) {
    asm volatile("mbarrier.init.shared.b64 [%0], %1;" :: "r"(a), "r"(cnt) : "memory");
}
__device__ __forceinline__ void mbar_wait(uint32_t a, uint32_t ph) {
    asm volatile(
        "{\n\t.reg .pred P;\n"
        "W_%=:\n\t"
        "mbarrier.try_wait.parity.acquire.cta.shared::cta.b64 P, [%0], %1, 0x989680;\n\t"
        "@P bra D_%=;\n\t"
        "bra W_%=;\n"
        "D_%=:\n\t}"
        :: "r"(a), "r"(ph) : "memory");
}
__device__ __forceinline__ void sts128(uint32_t a, uint32_t r0, uint32_t r1, uint32_t r2, uint32_t r3) {
    asm volatile("st.shared.v4.b32 [%0], {%1, %2, %3, %4};" :: "r"(a), "r"(r0), "r"(r1), "r"(r2), "r"(r3) : "memory");
}
__device__ __forceinline__ void mma_tf32_ts(uint32_t d, uint32_t a, uint64_t bd, uint32_t idesc, bool accum) {
    uint32_t en = accum ? 1u : 0u;
    asm volatile(
        "{\n\t.reg .pred p;\n\t"
        "setp.ne.u32 p, %5, 0;\n\t"
        "tcgen05.mma.cta_group::1.kind::tf32 [%0], [%1], %2, %3, {%4, %4, %4, %4}, p;\n\t}"
        :: "r"(d), "r"(a), "l"(bd), "r"(idesc), "r"(0u), "r"(en) : "memory");
}
__device__ __forceinline__ void mma_commit(uint32_t mbar) {
    asm volatile("tcgen05.commit.cta_group::1.mbarrier::arrive::one.shared::cluster.b64 [%0];" :: "r"(mbar) : "memory");
}
__device__ __forceinline__ uint64_t mk_desc(uint32_t addr) {
    const uint64_t base = (uint64_t(2) << 61) | (uint64_t(1) << 46) | (uint64_t(64) << 32) | (uint64_t(1) << 16);
    return base | ((uint64_t)(addr >> 4) & 0x3FFF);
}

#define LDTM32(r, a) \
    asm volatile( \
        "tcgen05.ld.sync.aligned.32x32b.x32.b32 " \
        "{%0, %1, %2, %3, %4, %5, %6, %7, " \
        " %8, %9, %10, %11, %12, %13, %14, %15, " \
        " %16, %17, %18, %19, %20, %21, %22, %23, " \
        " %24, %25, %26, %27, %28, %29, %30, %31}, [%32];" \
        : "=r"((r)[0]),  "=r"((r)[1]),  "=r"((r)[2]),  "=r"((r)[3]), \
          "=r"((r)[4]),  "=r"((r)[5]),  "=r"((r)[6]),  "=r"((r)[7]), \
          "=r"((r)[8]),  "=r"((r)[9]),  "=r"((r)[10]), "=r"((r)[11]), \
          "=r"((r)[12]), "=r"((r)[13]), "=r"((r)[14]), "=r"((r)[15]), \
          "=r"((r)[16]), "=r"((r)[17]), "=r"((r)[18]), "=r"((r)[19]), \
          "=r"((r)[20]), "=r"((r)[21]), "=r"((r)[22]), "=r"((r)[23]), \
          "=r"((r)[24]), "=r"((r)[25]), "=r"((r)[26]), "=r"((r)[27]), \
          "=r"((r)[28]), "=r"((r)[29]), "=r"((r)[30]), "=r"((r)[31]) \
        : "r"(a))

#define STTM32(a, r) \
    asm volatile( \
        "tcgen05.st.sync.aligned.32x32b.x32.b32 [%0], " \
        "{%1, %2, %3, %4, %5, %6, %7, %8, " \
        " %9, %10, %11, %12, %13, %14, %15, %16, " \
        " %17, %18, %19, %20, %21, %22, %23, %24, " \
        " %25, %26, %27, %28, %29, %30, %31, %32};" \
        :: "r"(a), \
           "r"((r)[0]),  "r"((r)[1]),  "r"((r)[2]),  "r"((r)[3]), \
           "r"((r)[4]),  "r"((r)[5]),  "r"((r)[6]),  "r"((r)[7]), \
           "r"((r)[8]),  "r"((r)[9]),  "r"((r)[10]), "r"((r)[11]), \
           "r"((r)[12]), "r"((r)[13]), "r"((r)[14]), "r"((r)[15]), \
           "r"((r)[16]), "r"((r)[17]), "r"((r)[18]), "r"((r)[19]), \
           "r"((r)[20]), "r"((r)[21]), "r"((r)[22]), "r"((r)[23]), \
           "r"((r)[24]), "r"((r)[25]), "r"((r)[26]), "r"((r)[27]), \
           "r"((r)[28]), "r"((r)[29]), "r"((r)[30]), "r"((r)[31]) \
        : "memory")

#define K4_IDESC ((1u<<4) | (2u<<7) | (2u<<10) | (16u<<17) | (8u<<24))

__device__ __forceinline__ void k4_load_tile_ca(uint32_t sdst, int row0, int tid)
{
    #pragma unroll
    for (int it = 0; it < 8; it++) {
        int f = tid + it * K4T;
        int r = f >> 5, q = f & 31;
        int kc = q >> 3, c4 = q & 7;
        uint32_t off = (uint32_t)(kc * 16384 + r * 128 + c4 * 16);
        off = off ^ ((off >> 3) & 0x70);
        int row = row0 + r;
        int ok = (row < VSZ);
        const float* gsrc = &g_wtf[(size_t)(ok ? row : 0) * CH + q * 4];
        int sz = ok ? 16 : 0;
        asm volatile("cp.async.cg.shared.global [%0], [%1], 16, %2;"
                     :: "r"(sdst + off), "l"(gsrc), "r"(sz) : "memory");
    }
}

// Epilogue v6: conflict-free LDS.128 + shfl alignment shift.
__device__ __forceinline__ void k4_epilogue(uint32_t dt, float* __restrict__ scr,
                                            int m0, int n0,
                                            float* __restrict__ out, int tid)
{
    int w = tid >> 5, lid = tid & 31;
    int row = (w & 3) * 32 + lid;
    int cb  = (w >> 2) * 32;
    uint32_t scr_u = s2u(scr);

    {
        uint32_t r[32];
        LDTM32(r, dt + cb);
        asm volatile("tcgen05.wait::ld.sync.aligned;" ::: "memory");
        #pragma unroll
        for (int gq = 0; gq < 8; gq++) {
            int cg = (cb >> 2) + gq;
            int sg = cg ^ (row & 31);
            sts128(scr_u + (uint32_t)(row * 128 + sg * 4) * 4,
                   r[4*gq], r[4*gq+1], r[4*gq+2], r[4*gq+3]);
        }
    }
    __syncthreads();

    if (n0 + 128 <= VSZ) {
        #pragma unroll
        for (int itr = 0; itr < 8; itr++) {
            int r2 = w * 8 + itr;
            int m  = m0 + r2;
            int c0 = (4 - (m & 3)) & 3;
            int sw = r2 & 31;
            float* orow = out + (size_t)m * VSZ + n0;

            int sg = lid ^ sw;
            float4 v = *(const float4*)&scr[r2 * 128 + sg * 4];

            if (c0 == 0) {
                *(float4*)(orow + 4 * lid) = v;
            } else {
                float vn0 = __shfl_down_sync(0xffffffffu, v.x, 1);
                float vn1 = __shfl_down_sync(0xffffffffu, v.y, 1);
                float vn2 = __shfl_down_sync(0xffffffffu, v.z, 1);
                float a0 = v.x, a1 = v.y, a2v = v.z, a3 = v.w;
                float4 o;
                if (c0 == 1)      { o.x = a1;  o.y = a2v; o.z = a3;  o.w = vn0; }
                else if (c0 == 2) { o.x = a2v; o.y = a3;  o.z = vn0; o.w = vn1; }
                else              { o.x = a3;  o.y = vn0; o.z = vn1; o.w = vn2; }
                if (lid < 31)
                    *(float4*)(orow + c0 + 4 * lid) = o;
                if (lid < c0)
                    orow[lid] = scr[r2 * 128 + (0 ^ sw) * 4 + lid];
                if (lid == 31) {
                    float tv[4] = { a0, a1, a2v, a3 };
                    #pragma unroll
                    for (int k = 0; k < 3; k++)
                        if (k < 4 - c0) orow[c0 + 124 + k] = tv[k + c0];
                }
            }
        }
    } else {
        for (int itr = 0; itr < 8; itr++) {
            int r2 = w * 8 + itr;
            int sw = r2 & 31;
            float* orow = out + (size_t)(m0 + r2) * VSZ;
            #pragma unroll
            for (int k = 0; k < 4; k++) {
                int col = lid + 32 * k;
                if (n0 + col < VSZ) {
                    int sg2 = (col >> 2) ^ sw;
                    orow[n0 + col] = scr[r2 * 128 + sg2 * 4 + (col & 3)];
                }
            }
        }
    }
}
#endif  // HAS_TCGEN05

__global__ void __launch_bounds__(K4T, 1) k4mma(const float* __restrict__ Wlm,
                                                float* __restrict__ out)
{
    extern __shared__ __align__(1024) char smem[];
    int tid = threadIdx.x;
    int c = blockIdx.x;
    int T0 = c * K4CHUNK;
    int T1 = T0 + K4CHUNK; if (T1 > K4SUP) T1 = K4SUP;

#if HAS_TCGEN05
    __shared__ __align__(16) unsigned long long s_mbar[2];
    __shared__ uint32_t s_tmem;

    int wid = tid >> 5;
    uint32_t sb = s2u(smem);
    float* scr = (float*)(smem + SCR);
    uint32_t mb[2] = { s2u(&s_mbar[0]), s2u(&s_mbar[1]) };

    if (wid == 0) {
        asm volatile("tcgen05.alloc.cta_group::1.sync.aligned.shared::cta.b32 [%0], %1;"
                     :: "r"(s2u(&s_tmem)), "r"(512u) : "memory");
        asm volatile("tcgen05.relinquish_alloc_permit.cta_group::1.sync.aligned;");
    }
    if (tid == 0) { mbar_init(mb[0], 1); mbar_init(mb[1], 1); }
    __syncthreads();
    uint32_t tmem;
    asm volatile("ld.shared.b32 %0, [%1];" : "=r"(tmem) : "r"(s2u(&s_tmem)));

    uint64_t bdesc[2] = { mk_desc(sb + SMB0), mk_desc(sb + SMB1) };
    int ph[2] = {0, 0};
    int s = 0;   // slot counter (B buffer parity)

    while (T0 < T1) {
        int mp = T0 / NTILES;
        int n0idx = T0 - mp * NTILES;
        int segend = (mp + 1) * NTILES; if (segend > T1) segend = T1;
        int nt = segend - T0;
        int m0 = mp * 256;   // pair base: rows m0..m0+255

        // A0, A1 -> TMEM (prev segment's MMAs drained by its final mbar waits)
        if (tid < 256) {
            int half = tid >> 7;            // 0 -> A0, 1 -> A1
            int lt = tid & 127;
            uint32_t warp_off = (uint32_t)(lt >> 5) << 21;
            uint32_t abase = half ? TM_A1 : TM_A0;
            const float* arow = &g_xf[(size_t)(m0 + half * 128 + lt) * CH];
            #pragma unroll
            for (int q = 0; q < 4; q++) {
                uint32_t ar[32];
                #pragma unroll
                for (int j = 0; j < 32; j++) ar[j] = f2tf(arow[q * 32 + j]);
                STTM32(tmem + abase + q * 32 + warp_off, ar);
            }
            asm volatile("tcgen05.wait::st.sync.aligned;" ::: "memory");
            asm volatile("tcgen05.fence::before_thread_sync;" ::: "memory");
        }
        // first B of segment
        k4_load_tile_ca(sb + ((s & 1) ? SMB1 : SMB0), n0idx * 128, tid);
        asm volatile("cp.async.commit_group;" ::: "memory");

        for (int i = 0; i < nt; i++) {
            int b = s & 1;
            int n0 = (n0idx + i) * 128;

            // B(n) visible; A ready; previous epilogues' scratch/TMEM reads done
            asm volatile("cp.async.wait_group 0;" ::: "memory");
            asm volatile("fence.proxy.async.shared::cta;" ::: "memory");
            __syncthreads();

            // split commits: D0 commit -> mb0, D1 commit -> mb1
            if (wid == 0 && elect1()) {
                asm volatile("tcgen05.fence::after_thread_sync;" ::: "memory");
                #pragma unroll
                for (int st = 0; st < 16; st++) {
                    uint64_t koff = (uint64_t)((st >> 2) * 1024 + (st & 3) * 2);
                    mma_tf32_ts(tmem + TM_D0, tmem + TM_A0 + st * 8,
                                bdesc[b] + koff, K4_IDESC, st > 0);
                }
                mma_commit(mb[0]);
                #pragma unroll
                for (int st = 0; st < 16; st++) {
                    uint64_t koff = (uint64_t)((st >> 2) * 1024 + (st & 3) * 2);
                    mma_tf32_ts(tmem + TM_D1, tmem + TM_A1 + st * 8,
                                bdesc[b] + koff, K4_IDESC, st > 0);
                }
                mma_commit(mb[1]);
            }

            // prefetch B(n+1) into the other buffer (overlaps both MMAs)
            if (i + 1 < nt) {
                k4_load_tile_ca(sb + ((b ^ 1) ? SMB1 : SMB0), (n0idx + i + 1) * 128, tid);
                asm volatile("cp.async.commit_group;" ::: "memory");
            }

            // epi(D0) overlaps the executing MMA(D1)
            mbar_wait(mb[0], ph[0]); ph[0] ^= 1;
            asm volatile("tcgen05.fence::after_thread_sync;" ::: "memory");
            k4_epilogue(tmem + TM_D0, scr, m0, n0, out, tid);
            __syncthreads();   // scratch reuse

            mbar_wait(mb[1], ph[1]); ph[1] ^= 1;
            asm volatile("tcgen05.fence::after_thread_sync;" ::: "memory");
            k4_epilogue(tmem + TM_D1, scr, m0 + 128, n0, out, tid);

            s++;
        }
        T0 = segend;
    }

    __syncthreads();
    if (wid == 0) {
        asm volatile("tcgen05.dealloc.cta_group::1.sync.aligned.b32 %0, %1;"
                     :: "r"(tmem), "r"(512u));
    }
#else
    // -------- fallback: plain fp32 smem GEMM (baseline sm_103 target) --------
    float* sA = (float*)(smem + SCR);
    float* sB = (float*)(smem + SMB0);

    int tx = tid & 31, ty = tid >> 5;

    while (T0 < T1) {
        int mp = T0 / NTILES;
        int n = T0 - mp * NTILES;
        int n0 = n * 128;

        for (int h = 0; h < 2; h++) {
            int m0 = mp * 256 + h * 128;
            __syncthreads();
            for (int i = tid; i < 128 * 32; i += K4T) {
                int r = i >> 5, q = i & 31;
                *(float4*)&sA[r * 128 + q * 4] = *(const float4*)&g_xf[(size_t)(m0 + r) * CH + q * 4];
            }
            for (int i = tid; i < 128 * 32; i += K4T) {
                int r = i >> 5, q = i & 31;
                float4 v = make_float4(0.f, 0.f, 0.f, 0.f);
                if (n0 + r < VSZ)
                    v = *(const float4*)&Wlm[(size_t)(n0 + r) * CH + q * 4];
                *(float4*)&sB[r * 128 + q * 4] = v;
            }
            __syncthreads();

            float acc[8][4];
            #pragma unroll
            for (int i = 0; i < 8; i++)
                #pragma unroll
                for (int j = 0; j < 4; j++) acc[i][j] = 0.f;

            for (int k = 0; k < 128; k++) {
                float a[8], b[4];
                #pragma unroll
                for (int i = 0; i < 8; i++) a[i] = sA[(ty * 8 + i) * 128 + k];
                #pragma unroll
                for (int j = 0; j < 4; j++) b[j] = sB[(tx * 4 + j) * 128 + k];
                #pragma unroll
                for (int i = 0; i < 8; i++)
                    #pragma unroll
                    for (int j = 0; j < 4; j++) acc[i][j] += a[i] * b[j];
            }

            #pragma unroll
            for (int i = 0; i < 8; i++) {
                float* row = out + (size_t)(m0 + ty * 8 + i) * VSZ;
                #pragma unroll
                for (int j = 0; j < 4; j++) {
                    int nn = n0 + tx * 4 + j;
                    if (nn < VSZ) row[nn] = acc[i][j];
                }
            }
        }
        T0++;
    }
#endif
}

// ==================== launch ====================
extern "C" void kernel_launch(void* const* d_in, const int* in_sizes, int n_in,
                              void* d_out, int out_size)
{
    const int*   ids    = (const int*)  d_in[0];
    const float* emb    = (const float*)d_in[1];
    const float* router = (const float*)d_in[2];
    const float* kexp   = (const float*)d_in[3];
    const float* vexp   = (const float*)d_in[4];
    const float* skv    = (const float*)d_in[5];
    const float* svv    = (const float*)d_in[6];
    const float* kvg    = (const float*)d_in[7];
    const float* Wq     = (const float*)d_in[8];
    const float* Wo     = (const float*)d_in[9];
    const float* Wm     = (const float*)d_in[10];
    const float* bm     = (const float*)d_in[11];
    const float* g1     = (const float*)d_in[12];
    const float* b1     = (const float*)d_in[13];
    const float* g2     = (const float*)d_in[14];
    const float* b2     = (const float*)d_in[15];
    const float* Wlm    = (const float*)d_in[16];

    float* out = (float*)d_out;
    float* gate_out = out + ((size_t)out_size - (size_t)TNUM * NE);

    cudaFuncSetAttribute(k4mma, cudaFuncAttributeMaxDynamicSharedMemorySize, K4_SMEM);
    cudaFuncSetAttribute(k123, cudaFuncAttributeMaxDynamicSharedMemorySize, F_SMEM);

    k0<<<((VSZ*CH/4) + 511) / 512, 512>>>(Wlm);
    k123<<<128, 256, F_SMEM>>>(ids, emb, router, Wq, g1, b1, gate_out,
                               kexp, vexp, skv, svv, kvg,
                               Wo, Wm, bm, g2, b2);
    k4mma<<<K4GRID, K4T, K4_SMEM>>>(Wlm, out);
}